// round 1
// baseline (speedup 1.0000x reference)
#include <cuda_runtime.h>
#include <cuda_bf16.h>
#include <cstdint>

// Problem constants
#define B_ 256
#define T_ 512
#define D_ 512
#define H_ 256
#define V_ 512
// 4H = 1024 gate columns, permuted to [i_j, f_j, g_j, o_j] interleave.

// ---------------- persistent device scratch (no allocations allowed) -------
__device__ float    g_embWp[2][V_][1024];                 // emb@W + b, gate-interleaved, fp32
__device__ float    g_Ufrag[2 * 8 * 32 * 16 * 32 * 2];    // U in mma-B-fragment-ready layout, tf32-rounded
__device__ float    g_H[2][2][B_][H_];                    // h exchange, double-buffered by step parity
__device__ unsigned g_cnt[2][8][T_];                      // arrival counters per (dir, m-chunk, step)

// ---------------- small helpers -------------------------------------------
__device__ __forceinline__ float tf32r(float x) {
    unsigned u;
    asm("cvt.rna.tf32.f32 %0, %1;" : "=r"(u) : "f"(x));
    return __uint_as_float(u);
}
__device__ __forceinline__ float sigf(float x) {
    return 1.f / (1.f + __expf(-x));   // saturates safely at extremes
}
__device__ __forceinline__ float tanh_(float x) {
    float t = __expf(2.f * fabsf(x));
    float r = 1.f - 2.f / (t + 1.f);   // t=inf -> r=1, safe
    return copysignf(r, x);
}
__device__ __forceinline__ void mma8(float* c, const unsigned* a, unsigned b0, unsigned b1) {
    asm volatile(
        "mma.sync.aligned.m16n8k8.row.col.f32.tf32.tf32.f32 "
        "{%0,%1,%2,%3}, {%4,%5,%6,%7}, {%8,%9}, {%0,%1,%2,%3};\n"
        : "+f"(c[0]), "+f"(c[1]), "+f"(c[2]), "+f"(c[3])
        : "r"(a[0]), "r"(a[1]), "r"(a[2]), "r"(a[3]), "r"(b0), "r"(b1));
}
__device__ __forceinline__ void spin_wait8(const unsigned* p) {
    unsigned v;
    while (true) {
        asm volatile("ld.acquire.gpu.b32 %0, [%1];" : "=r"(v) : "l"(p) : "memory");
        if (v >= 8u) break;
        __nanosleep(64);
    }
}

// ---------------- kernel 0: zero the arrival counters ----------------------
__global__ void zero_cnt_kernel() {
    int t = blockIdx.x * blockDim.x + threadIdx.x;
    if (t < 2 * 8 * T_) ((unsigned*)g_cnt)[t] = 0;
}

// ---------------- kernel 1: embWp[d][v][pcol] = (emb@W + b) permuted -------
// block: 256 threads computes tile [16 v][64 ocol]; grid (16 octiles, 32 vtiles, 2 dirs)
__global__ void precompute_embW(const float* __restrict__ emb,
                                const float* __restrict__ W_f, const float* __restrict__ b_f,
                                const float* __restrict__ W_b, const float* __restrict__ b_b) {
    const int d = blockIdx.z;
    const float* W  = d ? W_b : W_f;
    const float* bv = d ? b_b : b_f;
    const int oc = blockIdx.x * 64 + (threadIdx.x & 63);
    const int v0 = blockIdx.y * 16;
    __shared__ float sE[16 * 512];
    for (int i = threadIdx.x; i < 16 * 512; i += 256) sE[i] = emb[v0 * 512 + i];
    __syncthreads();
    const int vq = threadIdx.x >> 6;  // 0..3
    float acc[4] = {0.f, 0.f, 0.f, 0.f};
    for (int k = 0; k < 512; k++) {
        float wv = W[k * 1024 + oc];
#pragma unroll
        for (int i = 0; i < 4; i++) acc[i] += sE[(vq * 4 + i) * 512 + k] * wv;
    }
    const int g = oc >> 8;        // gate index (i,f,g,o blocks of 256)
    const int j = oc & 255;       // hidden unit
    const int pcol = j * 4 + g;   // interleaved column
    const float bb = bv[oc];
#pragma unroll
    for (int i = 0; i < 4; i++)
        g_embWp[d][v0 + vq * 4 + i][pcol] = acc[i] + bb;
}

// ---------------- kernel 2: U -> fragment-ready layout, tf32-rounded -------
// layout: [d][nchunk(8)][kc(32)][ns(16)][lane(32)][2]   (b0,b1 of mma B frag)
__global__ void build_Ufrag(const float* __restrict__ U_f, const float* __restrict__ U_b) {
    int t = blockIdx.x * blockDim.x + threadIdx.x;   // < 262144
    const int lane = t & 31;
    const int ns   = (t >> 5) & 15;
    const int kc   = (t >> 9) & 31;
    const int nc   = (t >> 14) & 7;
    const int d    = t >> 17;
    const float* U = d ? U_b : U_f;
    const int nl = ns * 8 + (lane >> 2);
    const int p  = nc * 128 + nl;       // permuted col
    const int j = p >> 2, g = p & 3;
    const int ocol = g * 256 + j;       // original col
    const int k0 = kc * 8 + (lane & 3);
    g_Ufrag[(size_t)t * 2 + 0] = tf32r(U[k0 * 1024 + ocol]);
    g_Ufrag[(size_t)t * 2 + 1] = tf32r(U[(k0 + 4) * 1024 + ocol]);
}

// ---------------- kernel 3: persistent bidirectional LSTM recurrence -------
// grid = 128 CTAs: bx -> d(2) x m-chunk(8, 32 batch rows) x n-chunk(8, 32 hidden cols = 128 gate cols)
// block = 128 threads (4 warps), each warp owns a 32(m) x 32(n) z-subtile.
#define SMEM_FLOATS (32768 + 10240 + 4224 + 1024 + 1024 + 32)
__global__ void __launch_bounds__(128, 1)
lstm_kernel(const int* __restrict__ token_ids) {
    extern __shared__ float smem[];
    float* sU   = smem;                // 32768: Ufrag slice [kc][ns16][lane][2]
    float* sHT  = sU + 32768;          // 10240: h transposed [k(256)][row pad 40]
    float* sZ   = sHT + 10240;         // 4224:  z tile [32][132]
    float* sC   = sZ + 4224;           // 1024:  c state [32][32]
    float* sH   = sC + 1024;           // 1024:  h state [32][32]
    int*   sTok = (int*)(sH + 1024);   // 32

    const int tid = threadIdx.x;
    const int bx  = blockIdx.x;
    const int d  = bx >> 6;
    const int m  = (bx >> 3) & 7;
    const int nc = bx & 7;
    const int l  = tid & 31, w = tid >> 5;
    const int l4 = l & 3, ld4 = l >> 2;

    // load this CTA's U slice (once) + zero local c/h state
    {
        const float4* src = (const float4*)&g_Ufrag[(size_t)(d * 8 + nc) * 32768];
        float4* dst = (float4*)sU;
        for (int i = tid; i < 8192; i += 128) dst[i] = src[i];
        for (int i = tid; i < 2048; i += 128) sC[i] = 0.f;   // covers sC and sH (contiguous)
    }
    __syncthreads();

    const float* gH  = &g_H[0][0][0][0];
    float*       gHw = &g_H[0][0][0][0];

    for (int s = 0; s < T_; s++) {
        const int tt = d ? (T_ - 1 - s) : s;

        if (tid < 32) sTok[tid] = token_ids[(m * 32 + tid) * T_ + tt];
        __syncthreads();

        // accumulator init C = xW(token) + bias  (fp32, gathered from embWp)
        float c_[2][4][4];
        {
            const int tk0 = sTok[ld4],      tk1 = sTok[ld4 + 8];
            const int tk2 = sTok[ld4 + 16], tk3 = sTok[ld4 + 24];
            const int tkq[2][2] = {{tk0, tk1}, {tk2, tk3}};
#pragma unroll
            for (int ms = 0; ms < 2; ms++) {
#pragma unroll
                for (int ns = 0; ns < 4; ns++) {
                    const int cb = w * 32 + ns * 8 + 2 * l4;
                    const float2 x0 = *(const float2*)&g_embWp[d][tkq[ms][0]][nc * 128 + cb];
                    const float2 x1 = *(const float2*)&g_embWp[d][tkq[ms][1]][nc * 128 + cb];
                    c_[ms][ns][0] = x0.x; c_[ms][ns][1] = x0.y;
                    c_[ms][ns][2] = x1.x; c_[ms][ns][3] = x1.y;
                }
            }
        }

        if (s > 0) {
            // wait for all 8 producers of h_{s-1} for this (d, m-chunk)
            if (tid == 0) spin_wait8(&g_cnt[d][m][s - 1]);
            __syncthreads();
            // stage h_{s-1}[32 rows][256 k] -> sHT[k][row] (pad 40: conflict-free A loads)
            const float* hsrc = gH + ((size_t)(d * 2 + ((s - 1) & 1)) * B_ + m * 32) * H_;
            for (int i = tid; i < 2048; i += 128) {
                const int row = i >> 6;
                const int kk  = (i & 63) << 2;
                const float4 v = *(const float4*)&hsrc[row * H_ + kk];
                sHT[(kk + 0) * 40 + row] = v.x;
                sHT[(kk + 1) * 40 + row] = v.y;
                sHT[(kk + 2) * 40 + row] = v.z;
                sHT[(kk + 3) * 40 + row] = v.w;
            }
            __syncthreads();

            // z += h @ U : 32 k-chunks of 8
#pragma unroll 4
            for (int kc = 0; kc < 32; kc++) {
                unsigned a[2][4];
#pragma unroll
                for (int ms = 0; ms < 2; ms++) {
                    const int rb = ms * 16 + ld4;
                    a[ms][0] = __float_as_uint(sHT[(kc * 8 + l4) * 40 + rb]);
                    a[ms][1] = __float_as_uint(sHT[(kc * 8 + l4) * 40 + rb + 8]);
                    a[ms][2] = __float_as_uint(sHT[(kc * 8 + 4 + l4) * 40 + rb]);
                    a[ms][3] = __float_as_uint(sHT[(kc * 8 + 4 + l4) * 40 + rb + 8]);
                }
#pragma unroll
                for (int ns = 0; ns < 4; ns++) {
                    const float2 bv = *(const float2*)&sU[((kc * 16 + w * 4 + ns) * 32 + l) * 2];
                    const unsigned b0 = __float_as_uint(bv.x), b1 = __float_as_uint(bv.y);
                    mma8(c_[0][ns], a[0], b0, b1);
                    mma8(c_[1][ns], a[1], b0, b1);
                }
            }
        }

        // write z fragments to smem
#pragma unroll
        for (int ms = 0; ms < 2; ms++) {
#pragma unroll
            for (int ns = 0; ns < 4; ns++) {
                const int cb = w * 32 + ns * 8 + 2 * l4;
                const int r  = ms * 16 + ld4;
                *(float2*)&sZ[r * 132 + cb]       = make_float2(c_[ms][ns][0], c_[ms][ns][1]);
                *(float2*)&sZ[(r + 8) * 132 + cb] = make_float2(c_[ms][ns][2], c_[ms][ns][3]);
            }
        }
        __syncthreads();

        // elementwise gates + state update + masked carry + h publish
        {
            const int row = tid >> 2;
            const int jb  = (tid & 3) * 8;
            const bool msk = (sTok[row] != 0);
            float hb_[8];
#pragma unroll
            for (int jj = 0; jj < 8; jj++) {
                const int j = jb + jj;
                const float4 z4 = *(const float4*)&sZ[row * 132 + 4 * j];
                const float cprev = sC[row * 32 + j];
                const float ii = sigf(z4.x);
                const float ff = sigf(z4.y);
                const float gg = tanh_(z4.z);
                const float oo = sigf(z4.w);
                const float cn = ff * cprev + ii * gg;
                const float hn = oo * tanh_(cn);
                const float cn2 = msk ? cn : cprev;
                const float hn2 = msk ? hn : sH[row * 32 + j];
                sC[row * 32 + j] = cn2;
                sH[row * 32 + j] = hn2;
                hb_[jj] = tf32r(hn2);
            }
            float* hdst = gHw + ((size_t)(d * 2 + (s & 1)) * B_ + m * 32 + row) * H_ + nc * 32 + jb;
            *(float4*)&hdst[0] = make_float4(hb_[0], hb_[1], hb_[2], hb_[3]);
            *(float4*)&hdst[4] = make_float4(hb_[4], hb_[5], hb_[6], hb_[7]);
        }
        __threadfence();
        __syncthreads();
        if (tid == 0) atomicAdd(&g_cnt[d][m][s], 1u);
    }
}

// ---------------- kernel 4: output projection ------------------------------
__global__ void output_kernel(const float* __restrict__ Wout, const float* __restrict__ bout,
                              float* __restrict__ out) {
    const int b = blockIdx.x * blockDim.x + threadIdx.x;
    if (b >= B_) return;
    float a0 = bout[0], a1 = bout[1];
    const float* hf = &g_H[0][1][b][0];  // final step s=511 -> parity 1
    const float* hb = &g_H[1][1][b][0];
    for (int k = 0; k < H_; k++) {
        const float f = hf[k], r = hb[k];
        a0 += f * Wout[2 * k]       + r * Wout[2 * (H_ + k)];
        a1 += f * Wout[2 * k + 1]   + r * Wout[2 * (H_ + k) + 1];
    }
    out[2 * b]     = a0;
    out[2 * b + 1] = a1;
}

// ---------------- launch ----------------------------------------------------
extern "C" void kernel_launch(void* const* d_in, const int* in_sizes, int n_in,
                              void* d_out, int out_size) {
    const int*   tok   = (const int*)d_in[0];
    const float* emb   = (const float*)d_in[1];
    const float* W_f   = (const float*)d_in[2];
    const float* U_f   = (const float*)d_in[3];
    const float* b_f   = (const float*)d_in[4];
    const float* W_b   = (const float*)d_in[5];
    const float* U_b   = (const float*)d_in[6];
    const float* b_b   = (const float*)d_in[7];
    const float* W_out = (const float*)d_in[8];
    const float* b_out = (const float*)d_in[9];
    float* out = (float*)d_out;

    const int smem_bytes = SMEM_FLOATS * 4;   // 197248
    cudaFuncSetAttribute(lstm_kernel, cudaFuncAttributeMaxDynamicSharedMemorySize, smem_bytes);

    zero_cnt_kernel<<<32, 256>>>();
    precompute_embW<<<dim3(16, 32, 2), 256>>>(emb, W_f, b_f, W_b, b_b);
    build_Ufrag<<<1024, 256>>>(U_f, U_b);
    lstm_kernel<<<128, 128, smem_bytes>>>(tok);
    output_kernel<<<1, 256>>>(W_out, b_out, out);
}

// round 2
// speedup vs baseline: 2.5371x; 2.5371x over previous
#include <cuda_runtime.h>
#include <cstdint>

// Problem constants
#define B_ 256
#define T_ 512
#define D_ 512
#define H_ 256
#define V_ 512

// ---------------- persistent device scratch --------------------------------
__device__ float    g_embWp[2][V_][1024];               // emb@W + b, gate-interleaved
__device__ float    g_Ufrag[2 * 8 * 32 * 16 * 32 * 2];  // U fragment-ready, tf32-rounded
__device__ float    g_HT[2 * 2 * 256 * 256];            // h exchange, TRANSPOSED [d][par][k][b]
__device__ unsigned g_cnt[2][8][T_];                    // arrival counters

// ---------------- helpers --------------------------------------------------
__device__ __forceinline__ float tf32r(float x) {
    unsigned u; asm("cvt.rna.tf32.f32 %0, %1;" : "=r"(u) : "f"(x));
    return __uint_as_float(u);
}
__device__ __forceinline__ float tapx(float x) {
    float r; asm("tanh.approx.f32 %0, %1;" : "=f"(r) : "f"(x));
    return r;
}
__device__ __forceinline__ float sigx(float x) {        // sigmoid via HW tanh (abs err ~1e-4)
    return fmaf(tapx(0.5f * x), 0.5f, 0.5f);
}
__device__ __forceinline__ float tanh_(float x) {       // exact-ish tanh (ex2-based)
    float t = __expf(2.f * fabsf(x));
    float r = 1.f - 2.f / (t + 1.f);
    return copysignf(r, x);
}
__device__ __forceinline__ void mma8(float* c, const unsigned* a, unsigned b0, unsigned b1) {
    asm volatile(
        "mma.sync.aligned.m16n8k8.row.col.f32.tf32.tf32.f32 "
        "{%0,%1,%2,%3}, {%4,%5,%6,%7}, {%8,%9}, {%0,%1,%2,%3};\n"
        : "+f"(c[0]), "+f"(c[1]), "+f"(c[2]), "+f"(c[3])
        : "r"(a[0]), "r"(a[1]), "r"(a[2]), "r"(a[3]), "r"(b0), "r"(b1));
}
__device__ __forceinline__ void spin_wait8(const unsigned* p) {
    unsigned v;
    while (true) {
        asm volatile("ld.acquire.gpu.b32 %0, [%1];" : "=r"(v) : "l"(p) : "memory");
        if (v >= 8u) break;
        __nanosleep(32);
    }
}

// ---------------- kernel 0: zero counters ----------------------------------
__global__ void zero_cnt_kernel() {
    int t = blockIdx.x * blockDim.x + threadIdx.x;
    if (t < 2 * 8 * T_) ((unsigned*)g_cnt)[t] = 0;
}

// ---------------- kernel 1: embW precompute (gate-interleaved) -------------
__global__ void precompute_embW(const float* __restrict__ emb,
                                const float* __restrict__ W_f, const float* __restrict__ b_f,
                                const float* __restrict__ W_b, const float* __restrict__ b_b) {
    const int d = blockIdx.z;
    const float* W  = d ? W_b : W_f;
    const float* bv = d ? b_b : b_f;
    const int oc = blockIdx.x * 64 + (threadIdx.x & 63);
    const int v0 = blockIdx.y * 16;
    __shared__ float sE[16 * 512];
    for (int i = threadIdx.x; i < 16 * 512; i += 256) sE[i] = emb[v0 * 512 + i];
    __syncthreads();
    const int vq = threadIdx.x >> 6;
    float acc[4] = {0.f, 0.f, 0.f, 0.f};
    for (int k = 0; k < 512; k++) {
        float wv = W[k * 1024 + oc];
#pragma unroll
        for (int i = 0; i < 4; i++) acc[i] += sE[(vq * 4 + i) * 512 + k] * wv;
    }
    const int g = oc >> 8, j = oc & 255;
    const int pcol = j * 4 + g;
    const float bb = bv[oc];
#pragma unroll
    for (int i = 0; i < 4; i++)
        g_embWp[d][v0 + vq * 4 + i][pcol] = acc[i] + bb;
}

// ---------------- kernel 2: U -> fragment layout ---------------------------
__global__ void build_Ufrag(const float* __restrict__ U_f, const float* __restrict__ U_b) {
    int t = blockIdx.x * blockDim.x + threadIdx.x;
    const int lane = t & 31;
    const int ns   = (t >> 5) & 15;
    const int kc   = (t >> 9) & 31;
    const int nc   = (t >> 14) & 7;
    const int d    = t >> 17;
    const float* U = d ? U_b : U_f;
    const int nl = ns * 8 + (lane >> 2);
    const int p  = nc * 128 + nl;
    const int j = p >> 2, g = p & 3;
    const int ocol = g * 256 + j;
    const int k0 = kc * 8 + (lane & 3);
    g_Ufrag[(size_t)t * 2 + 0] = tf32r(U[k0 * 1024 + ocol]);
    g_Ufrag[(size_t)t * 2 + 1] = tf32r(U[(k0 + 4) * 1024 + ocol]);
}

// ---------------- kernel 3: persistent recurrence --------------------------
// grid = 128: d(2) x m(8: 32 rows) x nc(8: 128 gate cols). block = 128 (4 warps).
#define SMEM_FLOATS (32768 + 10240 + 4224 + 1024 + 1024)
__global__ void __launch_bounds__(128, 1)
lstm_kernel(const int* __restrict__ token_ids) {
    extern __shared__ float smem[];
    float* sU  = smem;            // 32768: U frags [kc][ns16][lane][2]
    float* sHT = sU + 32768;      // 10240: h^T [k(256)][row pad 40]
    float* sZ  = sHT + 10240;     //  4224: z [32 rows][132]
    float* sC  = sZ + 4224;       //  1024: c state [j(32)][row(32)]
    float* sH  = sC + 1024;       //  1024: h state [j(32)][row(32)]

    const int tid = threadIdx.x;
    const int bx  = blockIdx.x;
    const int d  = bx >> 6;
    const int m  = (bx >> 3) & 7;
    const int nc = bx & 7;
    const int l  = tid & 31, w = tid >> 5;
    const int l4 = l & 3, ld4 = l >> 2;

    {   // load U slice + zero state
        const float4* src = (const float4*)&g_Ufrag[(size_t)(d * 8 + nc) * 32768];
        float4* dst = (float4*)sU;
        for (int i = tid; i < 8192; i += 128) dst[i] = src[i];
        for (int i = tid; i < 2048; i += 128) sC[i] = 0.f;  // sC + sH contiguous
    }
    __syncthreads();

    for (int s = 0; s < T_; s++) {
        const int tt = d ? (T_ - 1 - s) : s;

        // ---- early (pre-spin) loads: tokens + embW gather straight into accumulators
        const int rbase = m * 32;
        const int tk0 = token_ids[(rbase + ld4)      * T_ + tt];
        const int tk1 = token_ids[(rbase + ld4 + 8)  * T_ + tt];
        const int tk2 = token_ids[(rbase + ld4 + 16) * T_ + tt];
        const int tk3 = token_ids[(rbase + ld4 + 24) * T_ + tt];
        const int own_tok = token_ids[(rbase + l) * T_ + tt];

        float c_[2][4][4];
        {
            const float* e0 = g_embWp[d][tk0] + nc * 128;
            const float* e1 = g_embWp[d][tk1] + nc * 128;
            const float* e2 = g_embWp[d][tk2] + nc * 128;
            const float* e3 = g_embWp[d][tk3] + nc * 128;
#pragma unroll
            for (int ns = 0; ns < 4; ns++) {
                const int cb = w * 32 + ns * 8 + 2 * l4;
                float2 x0 = *(const float2*)(e0 + cb);
                float2 x1 = *(const float2*)(e1 + cb);
                float2 x2 = *(const float2*)(e2 + cb);
                float2 x3 = *(const float2*)(e3 + cb);
                c_[0][ns][0] = x0.x; c_[0][ns][1] = x0.y;
                c_[0][ns][2] = x1.x; c_[0][ns][3] = x1.y;
                c_[1][ns][0] = x2.x; c_[1][ns][1] = x2.y;
                c_[1][ns][2] = x3.x; c_[1][ns][3] = x3.y;
            }
        }

        if (s > 0) {
            // all threads spin (no broadcast barrier needed)
            spin_wait8(&g_cnt[d][m][s - 1]);

            // stage h^T: coalesced LDG.128 (L2 via .cg) + conflict-free STS.128
            const float* hsrc = g_HT + (size_t)((d * 2 + ((s - 1) & 1)) * 256) * 256 + m * 32;
#pragma unroll
            for (int it = 0; it < 16; it++) {
                const int i  = tid + it * 128;
                const int k  = i >> 3;
                const int rq = i & 7;
                float4 v = __ldcg((const float4*)(hsrc + k * 256 + rq * 4));
                *(float4*)&sHT[k * 40 + rq * 4] = v;
            }
            __syncthreads();

            // z += h @ U
#pragma unroll 4
            for (int kc = 0; kc < 32; kc++) {
                unsigned a[2][4];
#pragma unroll
                for (int ms = 0; ms < 2; ms++) {
                    const int rb = ms * 16 + ld4;
                    a[ms][0] = __float_as_uint(sHT[(kc * 8 + l4) * 40 + rb]);
                    a[ms][1] = __float_as_uint(sHT[(kc * 8 + l4) * 40 + rb + 8]);
                    a[ms][2] = __float_as_uint(sHT[(kc * 8 + 4 + l4) * 40 + rb]);
                    a[ms][3] = __float_as_uint(sHT[(kc * 8 + 4 + l4) * 40 + rb + 8]);
                }
#pragma unroll
                for (int ns = 0; ns < 4; ns++) {
                    const float2 bv = *(const float2*)&sU[((kc * 16 + w * 4 + ns) * 32 + l) * 2];
                    const unsigned b0 = __float_as_uint(bv.x), b1 = __float_as_uint(bv.y);
                    mma8(c_[0][ns], a[0], b0, b1);
                    mma8(c_[1][ns], a[1], b0, b1);
                }
            }
        }

        // ---- z fragments -> sZ (warp-private region: cols w*32..w*32+31)
#pragma unroll
        for (int ms = 0; ms < 2; ms++) {
#pragma unroll
            for (int ns = 0; ns < 4; ns++) {
                const int cb = w * 32 + ns * 8 + 2 * l4;
                const int r  = ms * 16 + ld4;
                *(float2*)&sZ[r * 132 + cb]       = make_float2(c_[ms][ns][0], c_[ms][ns][1]);
                *(float2*)&sZ[(r + 8) * 132 + cb] = make_float2(c_[ms][ns][2], c_[ms][ns][3]);
            }
        }
        __syncwarp();

        // ---- elementwise: row = lane, j = w*8..w*8+7 (same warp as z producer)
        {
            const bool msk = (own_tok != 0);
            const int jb = w * 8;
            float* hdst = g_HT + (size_t)((d * 2 + (s & 1)) * 256 + nc * 32 + jb) * 256 + rbase + l;
#pragma unroll
            for (int jj = 0; jj < 8; jj++) {
                const int j = jb + jj;
                const float4 z4 = *(const float4*)&sZ[l * 132 + 4 * j];
                const float cprev = sC[j * 32 + l];
                const float hprev = sH[j * 32 + l];
                const float ii = sigx(z4.x);
                const float ff = sigx(z4.y);
                const float gg = tanh_(z4.z);
                const float oo = sigx(z4.w);
                const float cn = fmaf(ff, cprev, ii * gg);
                const float hn = oo * tanh_(cn);
                const float cn2 = msk ? cn : cprev;
                const float hn2 = msk ? hn : hprev;
                sC[j * 32 + l] = cn2;
                sH[j * 32 + l] = hn2;
                hdst[jj * 256] = tf32r(hn2);   // fully coalesced STG.32
            }
        }
        __syncthreads();
        if (tid == 0)
            asm volatile("red.release.gpu.global.add.u32 [%0], %1;"
                         :: "l"(&g_cnt[d][m][s]), "r"(1u) : "memory");
    }
}

// ---------------- kernel 4: output projection ------------------------------
__global__ void output_kernel(const float* __restrict__ Wout, const float* __restrict__ bout,
                              float* __restrict__ out) {
    const int b = blockIdx.x * blockDim.x + threadIdx.x;
    if (b >= B_) return;
    float a0 = bout[0], a1 = bout[1];
    for (int k = 0; k < H_; k++) {
        const float f = g_HT[(size_t)((0 * 2 + 1) * 256 + k) * 256 + b];  // d=0, parity 1
        const float r = g_HT[(size_t)((1 * 2 + 1) * 256 + k) * 256 + b];  // d=1, parity 1
        a0 += f * Wout[2 * k]     + r * Wout[2 * (H_ + k)];
        a1 += f * Wout[2 * k + 1] + r * Wout[2 * (H_ + k) + 1];
    }
    out[2 * b]     = a0;
    out[2 * b + 1] = a1;
}

// ---------------- launch ----------------------------------------------------
extern "C" void kernel_launch(void* const* d_in, const int* in_sizes, int n_in,
                              void* d_out, int out_size) {
    const int*   tok   = (const int*)d_in[0];
    const float* emb   = (const float*)d_in[1];
    const float* W_f   = (const float*)d_in[2];
    const float* U_f   = (const float*)d_in[3];
    const float* b_f   = (const float*)d_in[4];
    const float* W_b   = (const float*)d_in[5];
    const float* U_b   = (const float*)d_in[6];
    const float* b_b   = (const float*)d_in[7];
    const float* W_out = (const float*)d_in[8];
    const float* b_out = (const float*)d_in[9];
    float* out = (float*)d_out;

    const int smem_bytes = SMEM_FLOATS * 4;
    cudaFuncSetAttribute(lstm_kernel, cudaFuncAttributeMaxDynamicSharedMemorySize, smem_bytes);

    zero_cnt_kernel<<<32, 256>>>();
    precompute_embW<<<dim3(16, 32, 2), 256>>>(emb, W_f, b_f, W_b, b_b);
    build_Ufrag<<<1024, 256>>>(U_f, U_b);
    lstm_kernel<<<128, 128, smem_bytes>>>(tok);
    output_kernel<<<1, 256>>>(W_out, b_out, out);
}

// round 3
// speedup vs baseline: 2.6118x; 1.0295x over previous
#include <cuda_runtime.h>
#include <cstdint>

#define B_ 256
#define T_ 512
#define D_ 512
#define H_ 256
#define V_ 512

// ---------------- persistent device scratch --------------------------------
__device__ float    g_embWp[2][V_][1024];                 // emb@W + b, gate-permuted cols
__device__ float    g_Ufrag[2 * 8 * 32 * 4 * 2 * 32 * 4]; // U b-frags [d][nc][kc][w][p][lane][4]
__device__ float    g_HA[2 * 2 * 8 * 8192];               // h exchange in A-frag layout [d][par][m][kc*2+ms][lane][4]
__device__ unsigned g_cnt[2][8][T_];                      // arrival counters

// ---------------- helpers --------------------------------------------------
__device__ __forceinline__ float tf32r(float x) {
    unsigned u; asm("cvt.rna.tf32.f32 %0, %1;" : "=r"(u) : "f"(x));
    return __uint_as_float(u);
}
__device__ __forceinline__ float tapx(float x) {
    float r; asm("tanh.approx.f32 %0, %1;" : "=f"(r) : "f"(x));
    return r;
}
__device__ __forceinline__ float sigx(float x) { return fmaf(tapx(0.5f * x), 0.5f, 0.5f); }
__device__ __forceinline__ float tanh_(float x) {
    float t = __expf(2.f * fabsf(x));
    float r = 1.f - 2.f / (t + 1.f);
    return copysignf(r, x);
}
__device__ __forceinline__ void mma8(float* c, const unsigned* a, unsigned b0, unsigned b1) {
    asm volatile(
        "mma.sync.aligned.m16n8k8.row.col.f32.tf32.tf32.f32 "
        "{%0,%1,%2,%3}, {%4,%5,%6,%7}, {%8,%9}, {%0,%1,%2,%3};\n"
        : "+f"(c[0]), "+f"(c[1]), "+f"(c[2]), "+f"(c[3])
        : "r"(a[0]), "r"(a[1]), "r"(a[2]), "r"(a[3]), "r"(b0), "r"(b1));
}
__device__ __forceinline__ void spin_wait8(const unsigned* p) {
    unsigned v;
    while (true) {
        asm volatile("ld.acquire.gpu.b32 %0, [%1];" : "=r"(v) : "l"(p) : "memory");
        if (v >= 8u) break;
        __nanosleep(32);
    }
}

// Gate/col permutation: col-block of 8 = (i_A,f_A,i_B,f_B,g_A,o_A,g_B,o_B)
// original col oc = gate*256 + j  ->  permuted p:
__host__ __device__ __forceinline__ int perm_col(int gate, int j) {
    return (j >> 5) * 128 + ((j >> 3) & 3) * 32 + ((j >> 1) & 3) * 8
         + (gate >> 1) * 4 + (j & 1) * 2 + (gate & 1);
}

// ---------------- kernel 0: zero counters ----------------------------------
__global__ void zero_cnt_kernel() {
    int t = blockIdx.x * blockDim.x + threadIdx.x;
    if (t < 2 * 8 * T_) ((unsigned*)g_cnt)[t] = 0;
}

// ---------------- kernel 1: embW precompute (permuted cols) ----------------
__global__ void precompute_embW(const float* __restrict__ emb,
                                const float* __restrict__ W_f, const float* __restrict__ b_f,
                                const float* __restrict__ W_b, const float* __restrict__ b_b) {
    const int d = blockIdx.z;
    const float* W  = d ? W_b : W_f;
    const float* bv = d ? b_b : b_f;
    const int oc = blockIdx.x * 64 + (threadIdx.x & 63);
    const int v0 = blockIdx.y * 16;
    __shared__ float sE[16 * 512];
    for (int i = threadIdx.x; i < 16 * 512; i += 256) sE[i] = emb[v0 * 512 + i];
    __syncthreads();
    const int vq = threadIdx.x >> 6;
    float acc[4] = {0.f, 0.f, 0.f, 0.f};
    for (int k = 0; k < 512; k++) {
        float wv = W[k * 1024 + oc];
#pragma unroll
        for (int i = 0; i < 4; i++) acc[i] += sE[(vq * 4 + i) * 512 + k] * wv;
    }
    const int gate = oc >> 8, j = oc & 255;
    const int pcol = perm_col(gate, j);
    const float bb = bv[oc];
#pragma unroll
    for (int i = 0; i < 4; i++)
        g_embWp[d][v0 + vq * 4 + i][pcol] = acc[i] + bb;
}

// ---------------- kernel 2: U -> b-frag layout -----------------------------
// sites: [d][nc][kc][w][p][lane], each writes float4 = (b0,b1 of ns=2p, b0,b1 of ns=2p+1)
__global__ void build_Ufrag(const float* __restrict__ U_f, const float* __restrict__ U_b) {
    int t = blockIdx.x * blockDim.x + threadIdx.x;   // < 131072
    if (t >= 131072) return;
    const int lane = t & 31;
    const int p    = (t >> 5) & 1;
    const int w    = (t >> 6) & 3;
    const int kc   = (t >> 8) & 31;
    const int nc   = (t >> 13) & 7;
    const int d    = (t >> 16) & 1;
    const float* U = d ? U_b : U_f;
    const int l4 = lane & 3, ld4 = lane >> 2;
    float v[4];
#pragma unroll
    for (int i = 0; i < 4; i++) {
        const int ns = 2 * p + (i >> 1);
        const int kk = kc * 8 + l4 + 4 * (i & 1);
        // permuted col pc = nc*128 + w*32 + ns*8 + ld4 ; decode to original
        const int o8 = ld4;
        const int gate = (o8 & 1) + 2 * (o8 >> 2);
        const int uSel = (o8 >> 1) & 1;
        const int j = nc * 32 + w * 8 + ns * 2 + uSel;
        v[i] = tf32r(U[kk * 1024 + gate * 256 + j]);
    }
    *(float4*)&g_Ufrag[(size_t)t * 4] = make_float4(v[0], v[1], v[2], v[3]);
}

// ---------------- kernel 3: persistent recurrence --------------------------
// grid = 128: d(2) x m(8) x nc(8). block = 128 (4 warps), warp w owns cols w*32..
#define SMEM_FLOATS (32768 + 8192)
__global__ void __launch_bounds__(128, 1)
lstm_kernel(const int* __restrict__ token_ids) {
    extern __shared__ float smem[];
    float* sU = smem;           // 32768: b-frags [kc][w][p][lane][4]
    float* sA = sU + 32768;     //  8192: a-frags [kc*2+ms][lane][4]

    const int tid = threadIdx.x;
    const int bx  = blockIdx.x;
    const int d  = bx >> 6;
    const int m  = (bx >> 3) & 7;
    const int nc = bx & 7;
    const int l  = tid & 31, w = tid >> 5;
    const int l4 = l & 3, ld4 = l >> 2;
    const bool hi4 = (l4 >= 2);

    {   // load U slice
        const float4* src = (const float4*)&g_Ufrag[(size_t)(d * 8 + nc) * 32768];
        float4* dst = (float4*)sU;
        for (int i = tid; i < 8192; i += 128) dst[i] = src[i];
    }
    __syncthreads();

    float cs[2][4], hs[2][4];
#pragma unroll
    for (int a = 0; a < 2; a++)
#pragma unroll
        for (int b = 0; b < 4; b++) { cs[a][b] = 0.f; hs[a][b] = 0.f; }

    const int rbase = m * 32;
    // publish address component: kc = nc*4 + w (fixed per warp)
    const int kcp = nc * 4 + w;

    for (int s = 0; s < T_; s++) {
        const int tt = d ? (T_ - 1 - s) : s;

        // ---- pre-spin loads: tokens + embW gather into accumulators
        const int tk0 = token_ids[(rbase + ld4)      * T_ + tt];
        const int tk1 = token_ids[(rbase + ld4 + 8)  * T_ + tt];
        const int tk2 = token_ids[(rbase + ld4 + 16) * T_ + tt];
        const int tk3 = token_ids[(rbase + ld4 + 24) * T_ + tt];

        float c_[2][4][4];
        {
            const float* e0 = g_embWp[d][tk0] + nc * 128;
            const float* e1 = g_embWp[d][tk1] + nc * 128;
            const float* e2 = g_embWp[d][tk2] + nc * 128;
            const float* e3 = g_embWp[d][tk3] + nc * 128;
#pragma unroll
            for (int ns = 0; ns < 4; ns++) {
                const int cb = w * 32 + ns * 8 + 2 * l4;
                float2 x0 = *(const float2*)(e0 + cb);
                float2 x1 = *(const float2*)(e1 + cb);
                float2 x2 = *(const float2*)(e2 + cb);
                float2 x3 = *(const float2*)(e3 + cb);
                c_[0][ns][0] = x0.x; c_[0][ns][1] = x0.y;
                c_[0][ns][2] = x1.x; c_[0][ns][3] = x1.y;
                c_[1][ns][0] = x2.x; c_[1][ns][1] = x2.y;
                c_[1][ns][2] = x3.x; c_[1][ns][3] = x3.y;
            }
        }

        if (s > 0) {
            spin_wait8(&g_cnt[d][m][s - 1]);

            // stage A-frags: pure linear copy (conflict-free both sides)
            const float* src = g_HA + (size_t)((d * 2 + ((s - 1) & 1)) * 8 + m) * 8192;
#pragma unroll
            for (int it = 0; it < 16; it++) {
                const int i = it * 128 + tid;
                float4 v = __ldcg((const float4*)(src + i * 4));
                *(float4*)&sA[i * 4] = v;
            }
            __syncthreads();

            // z += h @ U : per kc: 2 A LDS.128 + 2 B LDS.128 + 8 mma
#pragma unroll 4
            for (int kc = 0; kc < 32; kc++) {
                uint4 a0 = *(const uint4*)&sA[((kc * 2 + 0) * 32 + l) * 4];
                uint4 a1 = *(const uint4*)&sA[((kc * 2 + 1) * 32 + l) * 4];
                float4 b01 = *(const float4*)&sU[(((kc * 4 + w) * 2 + 0) * 32 + l) * 4];
                float4 b23 = *(const float4*)&sU[(((kc * 4 + w) * 2 + 1) * 32 + l) * 4];
                const unsigned* A0 = (const unsigned*)&a0;
                const unsigned* A1 = (const unsigned*)&a1;
                mma8(c_[0][0], A0, __float_as_uint(b01.x), __float_as_uint(b01.y));
                mma8(c_[1][0], A1, __float_as_uint(b01.x), __float_as_uint(b01.y));
                mma8(c_[0][1], A0, __float_as_uint(b01.z), __float_as_uint(b01.w));
                mma8(c_[1][1], A1, __float_as_uint(b01.z), __float_as_uint(b01.w));
                mma8(c_[0][2], A0, __float_as_uint(b23.x), __float_as_uint(b23.y));
                mma8(c_[1][2], A1, __float_as_uint(b23.x), __float_as_uint(b23.y));
                mma8(c_[0][3], A0, __float_as_uint(b23.z), __float_as_uint(b23.w));
                mma8(c_[1][3], A1, __float_as_uint(b23.z), __float_as_uint(b23.w));
            }
        }

        // ---- register elementwise: shuffle-exchange gates, state in regs
        float* hbase = g_HA + (size_t)((d * 2 + (s & 1)) * 8 + m) * 8192;
        const int tokc0 = hi4 ? tk1 : tk0;
        const int tokc1 = hi4 ? tk3 : tk2;
#pragma unroll
        for (int ms = 0; ms < 2; ms++) {
            const bool msk = (ms ? tokc1 : tokc0) != 0;
#pragma unroll
            for (int ns = 0; ns < 4; ns++) {
                // exchange with lane l^2 (l4: 0<->2, 1<->3)
                float s0 = hi4 ? c_[ms][ns][0] : c_[ms][ns][2];
                float s1 = hi4 ? c_[ms][ns][1] : c_[ms][ns][3];
                float r0 = __shfl_xor_sync(0xffffffffu, s0, 2);
                float r1 = __shfl_xor_sync(0xffffffffu, s1, 2);
                const float zi = hi4 ? r0 : c_[ms][ns][0];
                const float zf = hi4 ? r1 : c_[ms][ns][1];
                const float zg = hi4 ? c_[ms][ns][2] : r0;
                const float zo = hi4 ? c_[ms][ns][3] : r1;
                const float ii = sigx(zi);
                const float ff = sigx(zf);
                const float gg = tanh_(zg);
                const float oo = sigx(zo);
                const float cn = fmaf(ff, cs[ms][ns], ii * gg);
                const float hn = oo * tanh_(cn);
                const float cn2 = msk ? cn : cs[ms][ns];
                const float hn2 = msk ? hn : hs[ms][ns];
                cs[ms][ns] = cn2;
                hs[ms][ns] = hn2;
                // publish into A-frag layout
                const int l4p = (ns * 2 + (l4 & 1)) & 3;
                const int idx = 2 * (ns >> 1) + (hi4 ? 1 : 0);
                hbase[((size_t)(kcp * 2 + ms) * 32 + ld4 * 4 + l4p) * 4 + idx] = tf32r(hn2);
            }
        }
        __syncthreads();
        if (tid == 0)
            asm volatile("red.release.gpu.global.add.u32 [%0], %1;"
                         :: "l"(&g_cnt[d][m][s]), "r"(1u) : "memory");
    }
}

// ---------------- kernel 4: output projection ------------------------------
__global__ void output_kernel(const float* __restrict__ Wout, const float* __restrict__ bout,
                              float* __restrict__ out) {
    const int b = blockIdx.x * blockDim.x + threadIdx.x;
    if (b >= B_) return;
    float a0 = bout[0], a1 = bout[1];
    const int m = b >> 5, r = b & 31;
    const int ms = (r >> 4) & 1, ld4 = r & 7, hib = (r >> 3) & 1;
#pragma unroll 1
    for (int k = 0; k < H_; k++) {
        const int kc = k >> 3, l4p = k & 3, ki = (k >> 2) & 1;
        const size_t off = ((size_t)(kc * 2 + ms) * 32 + ld4 * 4 + l4p) * 4 + 2 * ki + hib;
        const float f = g_HA[(size_t)((0 * 2 + 1) * 8 + m) * 8192 + off];  // d=0, par=1
        const float rr = g_HA[(size_t)((1 * 2 + 1) * 8 + m) * 8192 + off]; // d=1, par=1
        a0 += f * Wout[2 * k]     + rr * Wout[2 * (H_ + k)];
        a1 += f * Wout[2 * k + 1] + rr * Wout[2 * (H_ + k) + 1];
    }
    out[2 * b]     = a0;
    out[2 * b + 1] = a1;
}

// ---------------- launch ----------------------------------------------------
extern "C" void kernel_launch(void* const* d_in, const int* in_sizes, int n_in,
                              void* d_out, int out_size) {
    const int*   tok   = (const int*)d_in[0];
    const float* emb   = (const float*)d_in[1];
    const float* W_f   = (const float*)d_in[2];
    const float* U_f   = (const float*)d_in[3];
    const float* b_f   = (const float*)d_in[4];
    const float* W_b   = (const float*)d_in[5];
    const float* U_b   = (const float*)d_in[6];
    const float* b_b   = (const float*)d_in[7];
    const float* W_out = (const float*)d_in[8];
    const float* b_out = (const float*)d_in[9];
    float* out = (float*)d_out;

    const int smem_bytes = SMEM_FLOATS * 4;   // 163840
    cudaFuncSetAttribute(lstm_kernel, cudaFuncAttributeMaxDynamicSharedMemorySize, smem_bytes);

    zero_cnt_kernel<<<32, 256>>>();
    precompute_embW<<<dim3(16, 32, 2), 256>>>(emb, W_f, b_f, W_b, b_b);
    build_Ufrag<<<512, 256>>>(U_f, U_b);
    lstm_kernel<<<128, 128, smem_bytes>>>(tok);
    output_kernel<<<1, 256>>>(W_out, b_out, out);
}

// round 4
// speedup vs baseline: 2.7603x; 1.0568x over previous
#include <cuda_runtime.h>
#include <cstdint>

#define B_ 256
#define T_ 512
#define D_ 512
#define H_ 256
#define V_ 512

// ---------------- persistent device scratch --------------------------------
__device__ float    g_embWp[2][V_][1024];                 // emb@W + b, gate-permuted cols
__device__ float    g_Ufrag[2 * 8 * 32 * 4 * 2 * 32 * 4]; // U b-frags [d][nc][kc][w][p][lane][4]
__device__ float    g_HA[2 * 2 * 8 * 8192];               // h exchange, A-frag layout [d][par][m][kc*2+ms][lane][4]
__device__ unsigned g_flag[2][8][32];                     // per-producer-warp step flags

// ---------------- helpers --------------------------------------------------
__device__ __forceinline__ float tf32r(float x) {
    unsigned u; asm("cvt.rna.tf32.f32 %0, %1;" : "=r"(u) : "f"(x));
    return __uint_as_float(u);
}
__device__ __forceinline__ float tapx(float x) {
    float r; asm("tanh.approx.f32 %0, %1;" : "=f"(r) : "f"(x));
    return r;
}
__device__ __forceinline__ float sigx(float x) { return fmaf(tapx(0.5f * x), 0.5f, 0.5f); }
__device__ __forceinline__ void mma8(float* c, const unsigned* a, unsigned b0, unsigned b1) {
    asm volatile(
        "mma.sync.aligned.m16n8k8.row.col.f32.tf32.tf32.f32 "
        "{%0,%1,%2,%3}, {%4,%5,%6,%7}, {%8,%9}, {%0,%1,%2,%3};\n"
        : "+f"(c[0]), "+f"(c[1]), "+f"(c[2]), "+f"(c[3])
        : "r"(a[0]), "r"(a[1]), "r"(a[2]), "r"(a[3]), "r"(b0), "r"(b1));
}
// all lanes poll their own flag; exit when every producer warp reached target
__device__ __forceinline__ void warp_wait32(const unsigned* flags, int l, unsigned target) {
    unsigned v;
    do {
        asm volatile("ld.acquire.gpu.global.b32 %0, [%1];" : "=r"(v) : "l"(flags + l) : "memory");
    } while (!__all_sync(0xffffffffu, v >= target));
    __syncwarp();
}

__host__ __device__ __forceinline__ int perm_col(int gate, int j) {
    return (j >> 5) * 128 + ((j >> 3) & 3) * 32 + ((j >> 1) & 3) * 8
         + (gate >> 1) * 4 + (j & 1) * 2 + (gate & 1);
}

// ---------------- kernel 0: zero flags --------------------------------------
__global__ void zero_cnt_kernel() {
    int t = blockIdx.x * blockDim.x + threadIdx.x;
    if (t < 2 * 8 * 32) ((unsigned*)g_flag)[t] = 0;
}

// ---------------- kernel 1: embW precompute (permuted cols) ----------------
__global__ void precompute_embW(const float* __restrict__ emb,
                                const float* __restrict__ W_f, const float* __restrict__ b_f,
                                const float* __restrict__ W_b, const float* __restrict__ b_b) {
    const int d = blockIdx.z;
    const float* W  = d ? W_b : W_f;
    const float* bv = d ? b_b : b_f;
    const int oc = blockIdx.x * 64 + (threadIdx.x & 63);
    const int v0 = blockIdx.y * 16;
    __shared__ float sE[16 * 512];
    for (int i = threadIdx.x; i < 16 * 512; i += 256) sE[i] = emb[v0 * 512 + i];
    __syncthreads();
    const int vq = threadIdx.x >> 6;
    float acc[4] = {0.f, 0.f, 0.f, 0.f};
    for (int k = 0; k < 512; k++) {
        float wv = W[k * 1024 + oc];
#pragma unroll
        for (int i = 0; i < 4; i++) acc[i] += sE[(vq * 4 + i) * 512 + k] * wv;
    }
    const int gate = oc >> 8, j = oc & 255;
    const int pcol = perm_col(gate, j);
    const float bb = bv[oc];
#pragma unroll
    for (int i = 0; i < 4; i++)
        g_embWp[d][v0 + vq * 4 + i][pcol] = acc[i] + bb;
}

// ---------------- kernel 2: U -> b-frag layout -----------------------------
__global__ void build_Ufrag(const float* __restrict__ U_f, const float* __restrict__ U_b) {
    int t = blockIdx.x * blockDim.x + threadIdx.x;
    if (t >= 131072) return;
    const int lane = t & 31;
    const int p    = (t >> 5) & 1;
    const int w    = (t >> 6) & 3;
    const int kc   = (t >> 8) & 31;
    const int nc   = (t >> 13) & 7;
    const int d    = (t >> 16) & 1;
    const float* U = d ? U_b : U_f;
    const int l4 = lane & 3, ld4 = lane >> 2;
    float v[4];
#pragma unroll
    for (int i = 0; i < 4; i++) {
        const int ns = 2 * p + (i >> 1);
        const int kk = kc * 8 + l4 + 4 * (i & 1);
        const int o8 = ld4;
        const int gate = (o8 & 1) + 2 * (o8 >> 2);
        const int uSel = (o8 >> 1) & 1;
        const int j = nc * 32 + w * 8 + ns * 2 + uSel;
        v[i] = tf32r(U[kk * 1024 + gate * 256 + j]);
    }
    *(float4*)&g_Ufrag[(size_t)t * 4] = make_float4(v[0], v[1], v[2], v[3]);
}

// ---------------- kernel 3: persistent recurrence --------------------------
// grid = 128: d(2) x m(8) x nc(8). block = 128 (4 warps); NO intra-loop barriers.
#define SMEM_FLOATS 32768
__global__ void __launch_bounds__(128, 1)
lstm_kernel(const int* __restrict__ token_ids) {
    extern __shared__ float smem[];
    float* sU = smem;           // 32768: b-frags [kc][w][p][lane][4]

    const int tid = threadIdx.x;
    const int bx  = blockIdx.x;
    const int d  = bx >> 6;
    const int m  = (bx >> 3) & 7;
    const int nc = bx & 7;
    const int l  = tid & 31, w = tid >> 5;
    const int l4 = l & 3, ld4 = l >> 2;
    const bool hi4 = (l4 >= 2);

    {   // load U slice (only shared state; read-only afterwards)
        const float4* src = (const float4*)&g_Ufrag[(size_t)(d * 8 + nc) * 32768];
        float4* dst = (float4*)sU;
        for (int i = tid; i < 8192; i += 128) dst[i] = src[i];
    }
    __syncthreads();

    float cs[2][4], hs[2][4];
#pragma unroll
    for (int a = 0; a < 2; a++)
#pragma unroll
        for (int b = 0; b < 4; b++) { cs[a][b] = 0.f; hs[a][b] = 0.f; }

    const int rbase = m * 32;
    const int kcp = nc * 4 + w;                 // this warp's producer slot
    const unsigned* myflags = &g_flag[d][m][0];

    for (int s = 0; s < T_; s++) {
        const int tt = d ? (T_ - 1 - s) : s;

        // ---- pre-wait loads: tokens + embW gather into accumulators
        const int tk0 = token_ids[(rbase + ld4)      * T_ + tt];
        const int tk1 = token_ids[(rbase + ld4 + 8)  * T_ + tt];
        const int tk2 = token_ids[(rbase + ld4 + 16) * T_ + tt];
        const int tk3 = token_ids[(rbase + ld4 + 24) * T_ + tt];

        float c_[2][4][4];
        {
            const float* e0 = g_embWp[d][tk0] + nc * 128;
            const float* e1 = g_embWp[d][tk1] + nc * 128;
            const float* e2 = g_embWp[d][tk2] + nc * 128;
            const float* e3 = g_embWp[d][tk3] + nc * 128;
#pragma unroll
            for (int ns = 0; ns < 4; ns++) {
                const int cb = w * 32 + ns * 8 + 2 * l4;
                float2 x0 = *(const float2*)(e0 + cb);
                float2 x1 = *(const float2*)(e1 + cb);
                float2 x2 = *(const float2*)(e2 + cb);
                float2 x3 = *(const float2*)(e3 + cb);
                c_[0][ns][0] = x0.x; c_[0][ns][1] = x0.y;
                c_[0][ns][2] = x1.x; c_[0][ns][3] = x1.y;
                c_[1][ns][0] = x2.x; c_[1][ns][1] = x2.y;
                c_[1][ns][2] = x3.x; c_[1][ns][3] = x3.y;
            }
        }

        if (s > 0) {
            // wait for all 32 producer warps of h_{s-1}
            warp_wait32(myflags, l, (unsigned)s);

            const float* src = g_HA + (size_t)((d * 2 + ((s - 1) & 1)) * 8 + m) * 8192;

            // depth-2 pipelined A loads (groups of 4 kc), direct from L2
            uint4 Abuf[2][8];
#pragma unroll
            for (int i = 0; i < 8; i++)
                Abuf[0][i] = __ldcg((const uint4*)(src + ((0 * 8 + i) * 32 + l) * 4));
#pragma unroll
            for (int i = 0; i < 8; i++)
                Abuf[1][i] = __ldcg((const uint4*)(src + ((1 * 8 + i) * 32 + l) * 4));

#pragma unroll
            for (int g = 0; g < 8; g++) {
#pragma unroll
                for (int i = 0; i < 4; i++) {
                    const int kc = g * 4 + i;
                    const unsigned* A0 = (const unsigned*)&Abuf[g & 1][2 * i];
                    const unsigned* A1 = (const unsigned*)&Abuf[g & 1][2 * i + 1];
                    float4 b01 = *(const float4*)&sU[(((kc * 4 + w) * 2 + 0) * 32 + l) * 4];
                    float4 b23 = *(const float4*)&sU[(((kc * 4 + w) * 2 + 1) * 32 + l) * 4];
                    mma8(c_[0][0], A0, __float_as_uint(b01.x), __float_as_uint(b01.y));
                    mma8(c_[1][0], A1, __float_as_uint(b01.x), __float_as_uint(b01.y));
                    mma8(c_[0][1], A0, __float_as_uint(b01.z), __float_as_uint(b01.w));
                    mma8(c_[1][1], A1, __float_as_uint(b01.z), __float_as_uint(b01.w));
                    mma8(c_[0][2], A0, __float_as_uint(b23.x), __float_as_uint(b23.y));
                    mma8(c_[1][2], A1, __float_as_uint(b23.x), __float_as_uint(b23.y));
                    mma8(c_[0][3], A0, __float_as_uint(b23.z), __float_as_uint(b23.w));
                    mma8(c_[1][3], A1, __float_as_uint(b23.z), __float_as_uint(b23.w));
                }
                if (g < 6) {
#pragma unroll
                    for (int i = 0; i < 8; i++)
                        Abuf[g & 1][i] =
                            __ldcg((const uint4*)(src + (((g + 2) * 8 + i) * 32 + l) * 4));
                }
            }
        }

        // ---- register elementwise (shuffle gate exchange), state in regs
        float* hbase = g_HA + (size_t)((d * 2 + (s & 1)) * 8 + m) * 8192;
        const int tokc0 = hi4 ? tk1 : tk0;
        const int tokc1 = hi4 ? tk3 : tk2;
#pragma unroll
        for (int ms = 0; ms < 2; ms++) {
            const bool msk = (ms ? tokc1 : tokc0) != 0;
#pragma unroll
            for (int ns = 0; ns < 4; ns++) {
                float s0 = hi4 ? c_[ms][ns][0] : c_[ms][ns][2];
                float s1 = hi4 ? c_[ms][ns][1] : c_[ms][ns][3];
                float r0 = __shfl_xor_sync(0xffffffffu, s0, 2);
                float r1 = __shfl_xor_sync(0xffffffffu, s1, 2);
                const float zi = hi4 ? r0 : c_[ms][ns][0];
                const float zf = hi4 ? r1 : c_[ms][ns][1];
                const float zg = hi4 ? c_[ms][ns][2] : r0;
                const float zo = hi4 ? c_[ms][ns][3] : r1;
                const float ii = sigx(zi);
                const float ff = sigx(zf);
                const float gg = tapx(zg);
                const float oo = sigx(zo);
                const float cn = fmaf(ff, cs[ms][ns], ii * gg);
                const float hn = oo * tapx(cn);
                const float cn2 = msk ? cn : cs[ms][ns];
                const float hn2 = msk ? hn : hs[ms][ns];
                cs[ms][ns] = cn2;
                hs[ms][ns] = hn2;
                const int l4p = (ns * 2 + (l4 & 1)) & 3;
                const int idx = 2 * (ns >> 1) + (hi4 ? 1 : 0);
                hbase[((size_t)(kcp * 2 + ms) * 32 + ld4 * 4 + l4p) * 4 + idx] = tf32r(hn2);
            }
        }
        __syncwarp();
        if (l == 0)
            asm volatile("st.release.gpu.global.b32 [%0], %1;"
                         :: "l"(myflags + kcp), "r"((unsigned)(s + 1)) : "memory");
    }
}

// ---------------- kernel 4: output projection ------------------------------
__global__ void output_kernel(const float* __restrict__ Wout, const float* __restrict__ bout,
                              float* __restrict__ out) {
    const int b = blockIdx.x * blockDim.x + threadIdx.x;
    if (b >= B_) return;
    float a0 = bout[0], a1 = bout[1];
    const int m = b >> 5, r = b & 31;
    const int ms = (r >> 4) & 1, ld4 = r & 7, hib = (r >> 3) & 1;
#pragma unroll 1
    for (int k = 0; k < H_; k++) {
        const int kc = k >> 3, l4p = k & 3, ki = (k >> 2) & 1;
        const size_t off = ((size_t)(kc * 2 + ms) * 32 + ld4 * 4 + l4p) * 4 + 2 * ki + hib;
        const float f  = g_HA[(size_t)((0 * 2 + 1) * 8 + m) * 8192 + off];
        const float rr = g_HA[(size_t)((1 * 2 + 1) * 8 + m) * 8192 + off];
        a0 += f * Wout[2 * k]     + rr * Wout[2 * (H_ + k)];
        a1 += f * Wout[2 * k + 1] + rr * Wout[2 * (H_ + k) + 1];
    }
    out[2 * b]     = a0;
    out[2 * b + 1] = a1;
}

// ---------------- launch ----------------------------------------------------
extern "C" void kernel_launch(void* const* d_in, const int* in_sizes, int n_in,
                              void* d_out, int out_size) {
    const int*   tok   = (const int*)d_in[0];
    const float* emb   = (const float*)d_in[1];
    const float* W_f   = (const float*)d_in[2];
    const float* U_f   = (const float*)d_in[3];
    const float* b_f   = (const float*)d_in[4];
    const float* W_b   = (const float*)d_in[5];
    const float* U_b   = (const float*)d_in[6];
    const float* b_b   = (const float*)d_in[7];
    const float* W_out = (const float*)d_in[8];
    const float* b_out = (const float*)d_in[9];
    float* out = (float*)d_out;

    const int smem_bytes = SMEM_FLOATS * 4;   // 131072
    cudaFuncSetAttribute(lstm_kernel, cudaFuncAttributeMaxDynamicSharedMemorySize, smem_bytes);

    zero_cnt_kernel<<<2, 256>>>();
    precompute_embW<<<dim3(16, 32, 2), 256>>>(emb, W_f, b_f, W_b, b_b);
    build_Ufrag<<<512, 256>>>(U_f, U_b);
    lstm_kernel<<<128, 128, smem_bytes>>>(tok);
    output_kernel<<<1, 256>>>(W_out, b_out, out);
}

// round 5
// speedup vs baseline: 3.1572x; 1.1438x over previous
#include <cuda_runtime.h>
#include <cuda_fp16.h>
#include <cstdint>

#define B_ 256
#define T_ 512
#define D_ 512
#define H_ 256
#define V_ 512

// ---------------- persistent device scratch --------------------------------
__device__ float    g_embWp[2][V_][1024];        // emb@W + b, gate-permuted cols (fp32)
__device__ uint4    g_Uf16[2 * 8 * 16 * 4 * 2 * 32];  // U fp16 b-frags [d][nc][kc16][wn4][p2][lane]
__device__ uint4    g_HA4[2 * 2 * 8 * 1024];     // h fp16 A-frags [d][par][m][kc16][ms2][lane] (uint4 = 4 regs)
__device__ unsigned g_flag[2][8][2][32];         // flags [d][m][w_m][producer slot]

// ---------------- helpers --------------------------------------------------
__device__ __forceinline__ float tapx(float x) {
    float r; asm("tanh.approx.f32 %0, %1;" : "=f"(r) : "f"(x));
    return r;
}
__device__ __forceinline__ float sigx(float x) { return fmaf(tapx(0.5f * x), 0.5f, 0.5f); }
__device__ __forceinline__ void mma16(float* c, const unsigned* a, unsigned b0, unsigned b1) {
    asm volatile(
        "mma.sync.aligned.m16n8k16.row.col.f32.f16.f16.f32 "
        "{%0,%1,%2,%3}, {%4,%5,%6,%7}, {%8,%9}, {%0,%1,%2,%3};\n"
        : "+f"(c[0]), "+f"(c[1]), "+f"(c[2]), "+f"(c[3])
        : "r"(a[0]), "r"(a[1]), "r"(a[2]), "r"(a[3]), "r"(b0), "r"(b1));
}
__device__ __forceinline__ void warp_wait32(const unsigned* flags, int l, unsigned target) {
    unsigned v;
    do {
        asm volatile("ld.acquire.gpu.global.b32 %0, [%1];" : "=r"(v) : "l"(flags + l) : "memory");
    } while (!__all_sync(0xffffffffu, v >= target));
    __syncwarp();
}
__host__ __device__ __forceinline__ int perm_col(int gate, int j) {
    return (j >> 5) * 128 + ((j >> 3) & 3) * 32 + ((j >> 1) & 3) * 8
         + (gate >> 1) * 4 + (j & 1) * 2 + (gate & 1);
}

// ---------------- kernel 0: zero flags --------------------------------------
__global__ void zero_cnt_kernel() {
    int t = blockIdx.x * blockDim.x + threadIdx.x;
    if (t < 2 * 8 * 2 * 32) ((unsigned*)g_flag)[t] = 0;
}

// ---------------- kernel 1: embW precompute (permuted cols, fp32) ----------
__global__ void precompute_embW(const float* __restrict__ emb,
                                const float* __restrict__ W_f, const float* __restrict__ b_f,
                                const float* __restrict__ W_b, const float* __restrict__ b_b) {
    const int d = blockIdx.z;
    const float* W  = d ? W_b : W_f;
    const float* bv = d ? b_b : b_f;
    const int oc = blockIdx.x * 64 + (threadIdx.x & 63);
    const int v0 = blockIdx.y * 16;
    __shared__ float sE[16 * 512];
    for (int i = threadIdx.x; i < 16 * 512; i += 256) sE[i] = emb[v0 * 512 + i];
    __syncthreads();
    const int vq = threadIdx.x >> 6;
    float acc[4] = {0.f, 0.f, 0.f, 0.f};
    for (int k = 0; k < 512; k++) {
        float wv = W[k * 1024 + oc];
#pragma unroll
        for (int i = 0; i < 4; i++) acc[i] += sE[(vq * 4 + i) * 512 + k] * wv;
    }
    const int gate = oc >> 8, j = oc & 255;
    const int pcol = perm_col(gate, j);
    const float bb = bv[oc];
#pragma unroll
    for (int i = 0; i < 4; i++)
        g_embWp[d][v0 + vq * 4 + i][pcol] = acc[i] + bb;
}

// ---------------- kernel 2: U -> fp16 b-frag layout ------------------------
// site t = [d][nc][kc16][wn4][p2][lane]; uint4 = (b0[ns=2p], b1[ns=2p], b0[ns=2p+1], b1[ns=2p+1])
// each b-reg packs halves (k, k+1), low half = even k.
__global__ void build_Uf16(const float* __restrict__ U_f, const float* __restrict__ U_b) {
    int t = blockIdx.x * blockDim.x + threadIdx.x;
    if (t >= 65536) return;
    const int lane = t & 31;
    const int p    = (t >> 5) & 1;
    const int w    = (t >> 6) & 3;
    const int kc   = (t >> 8) & 15;
    const int nc   = (t >> 12) & 7;
    const int d    = (t >> 15) & 1;
    const float* U = d ? U_b : U_f;
    const int l4 = lane & 3, ld4 = lane >> 2;
    const int o8 = ld4;                       // n-position within 8-col tile (permuted)
    const int gate = (o8 & 1) + 2 * (o8 >> 2);
    const int uSel = (o8 >> 1) & 1;
    unsigned vals[4];
#pragma unroll
    for (int i = 0; i < 4; i++) {
        const int ns = 2 * p + (i >> 1);
        const int k0 = kc * 16 + l4 * 2 + (i & 1) * 8;
        const int j  = nc * 32 + w * 8 + ns * 2 + uSel;
        const int col = gate * 256 + j;
        unsigned h0 = (unsigned)__half_as_ushort(__float2half_rn(U[k0 * 1024 + col]));
        unsigned h1 = (unsigned)__half_as_ushort(__float2half_rn(U[(k0 + 1) * 1024 + col]));
        vals[i] = h0 | (h1 << 16);
    }
    g_Uf16[t] = make_uint4(vals[0], vals[1], vals[2], vals[3]);
}

// ---------------- kernel 3: persistent recurrence (fp16 mma, 8 warps) ------
// grid = 128: d(2) x m(8) x nc(8). block = 256 = 8 warps: wid = w_m*4 + ... (w_n = wid&3, w_m = wid>>2)
// warp computes 16 rows (ms = w_m) x 32 gate-cols (w_n quarter). No intra-loop barriers.
__global__ void __launch_bounds__(256, 1)
lstm_kernel(const int* __restrict__ token_ids) {
    extern __shared__ uint4 sU[];   // 4096 uint4 = 64KB: [kc16][wn4][p2][lane]

    const int tid = threadIdx.x;
    const int bx  = blockIdx.x;
    const int d  = bx >> 6;
    const int m  = (bx >> 3) & 7;
    const int nc = bx & 7;
    const int wid = tid >> 5;
    const int w_n = wid & 3;
    const int w_m = wid >> 2;
    const int l  = tid & 31;
    const int l4 = l & 3, ld4 = l >> 2;
    const bool hi4 = (l4 >= 2);

    {   // load U slice
        const uint4* src = &g_Uf16[(d * 8 + nc) * 4096];
        for (int i = tid; i < 4096; i += 256) sU[i] = src[i];
    }
    __syncthreads();

    float cs[4], hs[4];
#pragma unroll
    for (int a = 0; a < 4; a++) { cs[a] = 0.f; hs[a] = 0.f; }

    const int rbase = m * 32;
    const unsigned* myflags = &g_flag[d][m][w_m][0];
    unsigned* myslot = &g_flag[d][m][w_m][nc * 4 + w_n];
    // producer address components
    const int kcP  = nc * 2 + (w_n >> 1);
    const int regP = (hi4 ? 1 : 0) + ((w_n & 1) ? 2 : 0);

    for (int s = 0; s < T_; s++) {
        const int tt = d ? (T_ - 1 - s) : s;

        // pre-wait loads: tokens for this warp's two row groups + embW gather
        const int row0 = rbase + w_m * 16 + ld4;
        const int t0 = token_ids[row0 * T_ + tt];
        const int t1 = token_ids[(row0 + 8) * T_ + tt];

        float c_[4][4];
        {
            const float* e0 = g_embWp[d][t0] + nc * 128 + w_n * 32;
            const float* e1 = g_embWp[d][t1] + nc * 128 + w_n * 32;
#pragma unroll
            for (int ns = 0; ns < 4; ns++) {
                const int cb = ns * 8 + 2 * l4;
                float2 x0 = *(const float2*)(e0 + cb);
                float2 x1 = *(const float2*)(e1 + cb);
                c_[ns][0] = x0.x; c_[ns][1] = x0.y;
                c_[ns][2] = x1.x; c_[ns][3] = x1.y;
            }
        }

        if (s > 0) {
            warp_wait32(myflags, l, (unsigned)s);

            const uint4* src = g_HA4 + ((d * 2 + ((s - 1) & 1)) * 8 + m) * 1024;
            uint4 A[16];
#pragma unroll
            for (int kc = 0; kc < 16; kc++)
                A[kc] = __ldcg(src + (kc * 2 + w_m) * 32 + l);

#pragma unroll
            for (int kc = 0; kc < 16; kc++) {
                uint4 bv0 = sU[((kc * 4 + w_n) * 2 + 0) * 32 + l];
                uint4 bv1 = sU[((kc * 4 + w_n) * 2 + 1) * 32 + l];
                const unsigned* Ar = (const unsigned*)&A[kc];
                mma16(c_[0], Ar, bv0.x, bv0.y);
                mma16(c_[1], Ar, bv0.z, bv0.w);
                mma16(c_[2], Ar, bv1.x, bv1.y);
                mma16(c_[3], Ar, bv1.z, bv1.w);
            }
        }

        // elementwise (register state) + fp16 pack + publish
        unsigned* hbase = (unsigned*)(g_HA4 + ((d * 2 + (s & 1)) * 8 + m) * 1024);
        const bool msk = (hi4 ? t1 : t0) != 0;
#pragma unroll
        for (int ns = 0; ns < 4; ns++) {
            float s0 = hi4 ? c_[ns][0] : c_[ns][2];
            float s1 = hi4 ? c_[ns][1] : c_[ns][3];
            float r0 = __shfl_xor_sync(0xffffffffu, s0, 2);
            float r1 = __shfl_xor_sync(0xffffffffu, s1, 2);
            const float zi = hi4 ? r0 : c_[ns][0];
            const float zf = hi4 ? r1 : c_[ns][1];
            const float zg = hi4 ? c_[ns][2] : r0;
            const float zo = hi4 ? c_[ns][3] : r1;
            const float ii = sigx(zi);
            const float ff = sigx(zf);
            const float gg = tapx(zg);
            const float oo = sigx(zo);
            const float cn = fmaf(ff, cs[ns], ii * gg);
            const float hn = oo * tapx(cn);
            const float cn2 = msk ? cn : cs[ns];
            const float hn2 = msk ? hn : hs[ns];
            cs[ns] = cn2;
            hs[ns] = hn2;
            // pack (even kj = low half) with lane^1 partner, even-l4 lanes store b32
            unsigned hb = (unsigned)__half_as_ushort(__float2half_rn(hn2));
            unsigned pb = __shfl_xor_sync(0xffffffffu, hb, 1);
            if ((l4 & 1) == 0) {
                unsigned word = (hb & 0xffffu) | (pb << 16);
                hbase[((kcP * 2 + w_m) * 32 + ld4 * 4 + ns) * 4 + regP] = word;
            }
        }
        __syncwarp();
        if (l == 0)
            asm volatile("st.release.gpu.global.b32 [%0], %1;"
                         :: "l"(myslot), "r"((unsigned)(s + 1)) : "memory");
    }
}

// ---------------- kernel 4: output projection ------------------------------
__global__ void output_kernel(const float* __restrict__ Wout, const float* __restrict__ bout,
                              float* __restrict__ out) {
    const int b = blockIdx.x * blockDim.x + threadIdx.x;
    if (b >= B_) return;
    float a0 = bout[0], a1 = bout[1];
    const int m = b >> 5, row = b & 31;
    const int ms = row >> 4, rlo = row & 15;
#pragma unroll 1
    for (int k = 0; k < H_; k++) {
        const int kc = k >> 4, kj = k & 15, kjl = kj & 7;
        const int lc = (rlo & 7) * 4 + (kjl >> 1);
        const int reg = ((rlo >= 8) ? 1 : 0) + ((kj >= 8) ? 2 : 0);
        const int off = ((kc * 2 + ms) * 32 + lc) * 4 + reg;
        unsigned uf = ((const unsigned*)(g_HA4 + ((0 * 2 + 1) * 8 + m) * 1024))[off];
        unsigned ur = ((const unsigned*)(g_HA4 + ((1 * 2 + 1) * 8 + m) * 1024))[off];
        unsigned sf = (kj & 1) ? (uf >> 16) : (uf & 0xffffu);
        unsigned sr = (kj & 1) ? (ur >> 16) : (ur & 0xffffu);
        const float f  = __half2float(__ushort_as_half((unsigned short)sf));
        const float rr = __half2float(__ushort_as_half((unsigned short)sr));
        a0 += f * Wout[2 * k]     + rr * Wout[2 * (H_ + k)];
        a1 += f * Wout[2 * k + 1] + rr * Wout[2 * (H_ + k) + 1];
    }
    out[2 * b]     = a0;
    out[2 * b + 1] = a1;
}

// ---------------- launch ----------------------------------------------------
extern "C" void kernel_launch(void* const* d_in, const int* in_sizes, int n_in,
                              void* d_out, int out_size) {
    const int*   tok   = (const int*)d_in[0];
    const float* emb   = (const float*)d_in[1];
    const float* W_f   = (const float*)d_in[2];
    const float* U_f   = (const float*)d_in[3];
    const float* b_f   = (const float*)d_in[4];
    const float* W_b   = (const float*)d_in[5];
    const float* U_b   = (const float*)d_in[6];
    const float* b_b   = (const float*)d_in[7];
    const float* W_out = (const float*)d_in[8];
    const float* b_out = (const float*)d_in[9];
    float* out = (float*)d_out;

    const int smem_bytes = 4096 * sizeof(uint4);   // 65536
    cudaFuncSetAttribute(lstm_kernel, cudaFuncAttributeMaxDynamicSharedMemorySize, smem_bytes);

    zero_cnt_kernel<<<4, 256>>>();
    precompute_embW<<<dim3(16, 32, 2), 256>>>(emb, W_f, b_f, W_b, b_b);
    build_Uf16<<<256, 256>>>(U_f, U_b);
    lstm_kernel<<<128, 256, smem_bytes>>>(tok);
    output_kernel<<<1, 256>>>(W_out, b_out, out);
}

// round 6
// speedup vs baseline: 3.5145x; 1.1132x over previous
#include <cuda_runtime.h>
#include <cuda_fp16.h>
#include <cstdint>

#define B_ 256
#define T_ 512
#define D_ 512
#define H_ 256
#define V_ 512

// ---------------- persistent device scratch --------------------------------
__device__ float    g_embWp[2][V_][1024];             // emb@W + b, gate-permuted cols (fp32)
__device__ uint4    g_Uf16[2 * 8 * 16 * 4 * 2 * 32];  // U fp16 b-frags [d][nc][kc16][wn4][p2][lane]
__device__ uint4    g_HA4[2 * 2 * 8 * 1024];          // h fp16 A-frags [d][par][m][kc16][ms2][lane]
__device__ unsigned g_flag[2][8][2][8][4];            // flags [d][m][w_m][src_nc][w_n]

// ---------------- helpers --------------------------------------------------
__device__ __forceinline__ float tapx(float x) {
    float r; asm("tanh.approx.f32 %0, %1;" : "=f"(r) : "f"(x));
    return r;
}
__device__ __forceinline__ float sigx(float x) { return fmaf(tapx(0.5f * x), 0.5f, 0.5f); }
__device__ __forceinline__ void mma16(float* c, const unsigned* a, unsigned b0, unsigned b1) {
    asm volatile(
        "mma.sync.aligned.m16n8k16.row.col.f32.f16.f16.f32 "
        "{%0,%1,%2,%3}, {%4,%5,%6,%7}, {%8,%9}, {%0,%1,%2,%3};\n"
        : "+f"(c[0]), "+f"(c[1]), "+f"(c[2]), "+f"(c[3])
        : "r"(a[0]), "r"(a[1]), "r"(a[2]), "r"(a[3]), "r"(b0), "r"(b1));
}
// one k16-chunk of the recurrence: 2 B LDS.128 + 4 mma into c[0..3]
__device__ __forceinline__ void chunk_mma(float (*c)[4], const uint4* sU, int kc,
                                          int w_n, int l, uint4 A) {
    uint4 bv0 = sU[((kc * 4 + w_n) * 2 + 0) * 32 + l];
    uint4 bv1 = sU[((kc * 4 + w_n) * 2 + 1) * 32 + l];
    const unsigned* Ar = (const unsigned*)&A;
    mma16(c[0], Ar, bv0.x, bv0.y);
    mma16(c[1], Ar, bv0.z, bv0.w);
    mma16(c[2], Ar, bv1.x, bv1.y);
    mma16(c[3], Ar, bv1.z, bv1.w);
}
__host__ __device__ __forceinline__ int perm_col(int gate, int j) {
    return (j >> 5) * 128 + ((j >> 3) & 3) * 32 + ((j >> 1) & 3) * 8
         + (gate >> 1) * 4 + (j & 1) * 2 + (gate & 1);
}

// ---------------- kernel 0: zero flags --------------------------------------
__global__ void zero_cnt_kernel() {
    int t = blockIdx.x * blockDim.x + threadIdx.x;
    if (t < 2 * 8 * 2 * 8 * 4) ((unsigned*)g_flag)[t] = 0;
}

// ---------------- kernel 1: embW precompute (permuted cols, fp32) ----------
__global__ void precompute_embW(const float* __restrict__ emb,
                                const float* __restrict__ W_f, const float* __restrict__ b_f,
                                const float* __restrict__ W_b, const float* __restrict__ b_b) {
    const int d = blockIdx.z;
    const float* W  = d ? W_b : W_f;
    const float* bv = d ? b_b : b_f;
    const int oc = blockIdx.x * 64 + (threadIdx.x & 63);
    const int v0 = blockIdx.y * 16;
    __shared__ float sE[16 * 512];
    for (int i = threadIdx.x; i < 16 * 512; i += 256) sE[i] = emb[v0 * 512 + i];
    __syncthreads();
    const int vq = threadIdx.x >> 6;
    float acc[4] = {0.f, 0.f, 0.f, 0.f};
    for (int k = 0; k < 512; k++) {
        float wv = W[k * 1024 + oc];
#pragma unroll
        for (int i = 0; i < 4; i++) acc[i] += sE[(vq * 4 + i) * 512 + k] * wv;
    }
    const int gate = oc >> 8, j = oc & 255;
    const int pcol = perm_col(gate, j);
    const float bb = bv[oc];
#pragma unroll
    for (int i = 0; i < 4; i++)
        g_embWp[d][v0 + vq * 4 + i][pcol] = acc[i] + bb;
}

// ---------------- kernel 2: U -> fp16 b-frag layout ------------------------
__global__ void build_Uf16(const float* __restrict__ U_f, const float* __restrict__ U_b) {
    int t = blockIdx.x * blockDim.x + threadIdx.x;
    if (t >= 65536) return;
    const int lane = t & 31;
    const int p    = (t >> 5) & 1;
    const int w    = (t >> 6) & 3;
    const int kc   = (t >> 8) & 15;
    const int nc   = (t >> 12) & 7;
    const int d    = (t >> 15) & 1;
    const float* U = d ? U_b : U_f;
    const int l4 = lane & 3, ld4 = lane >> 2;
    const int o8 = ld4;
    const int gate = (o8 & 1) + 2 * (o8 >> 2);
    const int uSel = (o8 >> 1) & 1;
    unsigned vals[4];
#pragma unroll
    for (int i = 0; i < 4; i++) {
        const int ns = 2 * p + (i >> 1);
        const int k0 = kc * 16 + l4 * 2 + (i & 1) * 8;
        const int j  = nc * 32 + w * 8 + ns * 2 + uSel;
        const int col = gate * 256 + j;
        unsigned h0 = (unsigned)__half_as_ushort(__float2half_rn(U[k0 * 1024 + col]));
        unsigned h1 = (unsigned)__half_as_ushort(__float2half_rn(U[(k0 + 1) * 1024 + col]));
        vals[i] = h0 | (h1 << 16);
    }
    g_Uf16[t] = make_uint4(vals[0], vals[1], vals[2], vals[3]);
}

// ---------------- kernel 3: persistent recurrence (adaptive sources) -------
// grid = 128: d(2) x m(8) x nc(8). block = 256 = 8 warps (w_m 2 x w_n 4).
__global__ void __launch_bounds__(256, 1)
lstm_kernel(const int* __restrict__ token_ids) {
    extern __shared__ uint4 smem4[];
    uint4* sU     = smem4;            // 4096 uint4 = 64KB
    uint4* sSelf4 = smem4 + 4096;     //  256 uint4 =  4KB: [par2][kcL*2+w_m][lane]
    unsigned* sSelfW = (unsigned*)sSelf4;

    const int tid = threadIdx.x;
    const int bx  = blockIdx.x;
    const int d  = bx >> 6;
    const int m  = (bx >> 3) & 7;
    const int nc = bx & 7;
    const int wid = tid >> 5;
    const int w_n = wid & 3;
    const int w_m = wid >> 2;
    const int l  = tid & 31;
    const int l4 = l & 3, ld4 = l >> 2;
    const bool hi4 = (l4 >= 2);

    {   // load U slice
        const uint4* src = &g_Uf16[(d * 8 + nc) * 4096];
        for (int i = tid; i < 4096; i += 256) sU[i] = src[i];
    }
    __syncthreads();

    float cs[4], hs[4];
#pragma unroll
    for (int a = 0; a < 4; a++) { cs[a] = 0.f; hs[a] = 0.f; }

    const int rbase = m * 32;
    const unsigned* myflags = &g_flag[d][m][w_m][0][0];
    unsigned* myslot = &g_flag[d][m][w_m][nc][w_n];
    const int kcP  = nc * 2 + (w_n >> 1);
    const int regP = (hi4 ? 1 : 0) + ((w_n & 1) ? 2 : 0);
    const int kcL  = w_n >> 1;

    for (int s = 0; s < T_; s++) {
        const int tt = d ? (T_ - 1 - s) : s;

        const int row0 = rbase + w_m * 16 + ld4;
        const int t0 = token_ids[row0 * T_ + tt];
        const int t1 = token_ids[(row0 + 8) * T_ + tt];

        float cA[4][4], cB[4][4];
        {
            const float* e0 = g_embWp[d][t0] + nc * 128 + w_n * 32;
            const float* e1 = g_embWp[d][t1] + nc * 128 + w_n * 32;
#pragma unroll
            for (int ns = 0; ns < 4; ns++) {
                const int cb = ns * 8 + 2 * l4;
                float2 x0 = *(const float2*)(e0 + cb);
                float2 x1 = *(const float2*)(e1 + cb);
                cA[ns][0] = x0.x; cA[ns][1] = x0.y;
                cA[ns][2] = x1.x; cA[ns][3] = x1.y;
                cB[ns][0] = 0.f; cB[ns][1] = 0.f; cB[ns][2] = 0.f; cB[ns][3] = 0.f;
            }
        }

        if (s > 0) {
            const unsigned tgt = (unsigned)s;
            const int par = (s - 1) & 1;
            const uint4* gsrc = g_HA4 + ((d * 2 + par) * 8 + m) * 1024;

            // ---- self slice first, from local smem (no global, no flags)
            {
                uint4 A0 = sSelf4[par * 128 + (0 * 2 + w_m) * 32 + l];
                uint4 A1 = sSelf4[par * 128 + (1 * 2 + w_m) * 32 + l];
                chunk_mma(cA, sU, nc * 2 + 0, w_n, l, A0);
                chunk_mma(cB, sU, nc * 2 + 1, w_n, l, A1);
            }

            // ---- remote slices, processed in arrival order
            unsigned pend = 0xFFu & ~(1u << nc);
            while (pend) {
                unsigned avail = 0;
                do {
                    unsigned v;
                    asm volatile("ld.acquire.gpu.global.b32 %0, [%1];"
                                 : "=r"(v) : "l"(myflags + l) : "memory");
                    unsigned rdy = __ballot_sync(0xffffffffu, v >= tgt);
                    unsigned x = rdy & (rdy >> 1) & (rdy >> 2) & (rdy >> 3);
                    unsigned m8 = 0;
#pragma unroll
                    for (int j = 0; j < 8; j++) m8 |= ((x >> (4 * j)) & 1u) << j;
                    avail = m8 & pend;
                } while (!avail);

                int j0, j1 = -1, j2 = -1, j3 = -1;
                j0 = __ffs(avail) - 1; avail &= avail - 1;
                if (avail) { j1 = __ffs(avail) - 1; avail &= avail - 1;
                    if (avail) { j2 = __ffs(avail) - 1; avail &= avail - 1;
                        if (avail) { j3 = __ffs(avail) - 1; avail &= avail - 1; } } }
                pend &= ~(1u << j0);
                if (j1 >= 0) pend &= ~(1u << j1);
                if (j2 >= 0) pend &= ~(1u << j2);
                if (j3 >= 0) pend &= ~(1u << j3);

                // batch loads ahead of mma for all grabbed sources
                uint4 a00, a01, a10, a11, a20, a21, a30, a31;
                a00 = __ldcg(gsrc + ((j0 * 2 + 0) * 2 + w_m) * 32 + l);
                a01 = __ldcg(gsrc + ((j0 * 2 + 1) * 2 + w_m) * 32 + l);
                if (j1 >= 0) {
                    a10 = __ldcg(gsrc + ((j1 * 2 + 0) * 2 + w_m) * 32 + l);
                    a11 = __ldcg(gsrc + ((j1 * 2 + 1) * 2 + w_m) * 32 + l);
                }
                if (j2 >= 0) {
                    a20 = __ldcg(gsrc + ((j2 * 2 + 0) * 2 + w_m) * 32 + l);
                    a21 = __ldcg(gsrc + ((j2 * 2 + 1) * 2 + w_m) * 32 + l);
                }
                if (j3 >= 0) {
                    a30 = __ldcg(gsrc + ((j3 * 2 + 0) * 2 + w_m) * 32 + l);
                    a31 = __ldcg(gsrc + ((j3 * 2 + 1) * 2 + w_m) * 32 + l);
                }
                chunk_mma(cA, sU, j0 * 2 + 0, w_n, l, a00);
                chunk_mma(cB, sU, j0 * 2 + 1, w_n, l, a01);
                if (j1 >= 0) {
                    chunk_mma(cA, sU, j1 * 2 + 0, w_n, l, a10);
                    chunk_mma(cB, sU, j1 * 2 + 1, w_n, l, a11);
                }
                if (j2 >= 0) {
                    chunk_mma(cA, sU, j2 * 2 + 0, w_n, l, a20);
                    chunk_mma(cB, sU, j2 * 2 + 1, w_n, l, a21);
                }
                if (j3 >= 0) {
                    chunk_mma(cA, sU, j3 * 2 + 0, w_n, l, a30);
                    chunk_mma(cB, sU, j3 * 2 + 1, w_n, l, a31);
                }
            }
        }

        // ---- merge split accumulators
        float c_[4][4];
#pragma unroll
        for (int ns = 0; ns < 4; ns++)
#pragma unroll
            for (int i = 0; i < 4; i++) c_[ns][i] = cA[ns][i] + cB[ns][i];

        // ---- elementwise (register state) + fp16 pack + publish (global + smem mirror)
        unsigned* hbase = (unsigned*)(g_HA4 + ((d * 2 + (s & 1)) * 8 + m) * 1024);
        const int parw = (s & 1) * 512;
        const bool msk = (hi4 ? t1 : t0) != 0;
#pragma unroll
        for (int ns = 0; ns < 4; ns++) {
            float s0 = hi4 ? c_[ns][0] : c_[ns][2];
            float s1 = hi4 ? c_[ns][1] : c_[ns][3];
            float r0 = __shfl_xor_sync(0xffffffffu, s0, 2);
            float r1 = __shfl_xor_sync(0xffffffffu, s1, 2);
            const float zi = hi4 ? r0 : c_[ns][0];
            const float zf = hi4 ? r1 : c_[ns][1];
            const float zg = hi4 ? c_[ns][2] : r0;
            const float zo = hi4 ? c_[ns][3] : r1;
            const float ii = sigx(zi);
            const float ff = sigx(zf);
            const float gg = tapx(zg);
            const float oo = sigx(zo);
            const float cn = fmaf(ff, cs[ns], ii * gg);
            const float hn = oo * tapx(cn);
            const float cn2 = msk ? cn : cs[ns];
            const float hn2 = msk ? hn : hs[ns];
            cs[ns] = cn2;
            hs[ns] = hn2;
            unsigned hb = (unsigned)__half_as_ushort(__float2half_rn(hn2));
            unsigned pb = __shfl_xor_sync(0xffffffffu, hb, 1);
            if ((l4 & 1) == 0) {
                unsigned word = (hb & 0xffffu) | (pb << 16);
                const int wofs = ((kcP * 2 + w_m) * 32 + ld4 * 4 + ns) * 4 + regP;
                hbase[wofs] = word;
                sSelfW[parw + ((kcL * 2 + w_m) * 32 + ld4 * 4 + ns) * 4 + regP] = word;
            }
        }
        __syncwarp();
        if (l == 0)
            asm volatile("st.release.gpu.global.b32 [%0], %1;"
                         :: "l"(myslot), "r"((unsigned)(s + 1)) : "memory");
        // intra-group barrier: makes smem mirror visible + protects parity reuse
        asm volatile("bar.sync %0, %1;" :: "r"(1 + w_m), "r"(128) : "memory");
    }
}

// ---------------- kernel 4: output projection ------------------------------
__global__ void output_kernel(const float* __restrict__ Wout, const float* __restrict__ bout,
                              float* __restrict__ out) {
    const int b = blockIdx.x * blockDim.x + threadIdx.x;
    if (b >= B_) return;
    float a0 = bout[0], a1 = bout[1];
    const int m = b >> 5, row = b & 31;
    const int ms = row >> 4, rlo = row & 15;
#pragma unroll 1
    for (int k = 0; k < H_; k++) {
        const int kc = k >> 4, kj = k & 15, kjl = kj & 7;
        const int lc = (rlo & 7) * 4 + (kjl >> 1);
        const int reg = ((rlo >= 8) ? 1 : 0) + ((kj >= 8) ? 2 : 0);
        const int off = ((kc * 2 + ms) * 32 + lc) * 4 + reg;
        unsigned uf = ((const unsigned*)(g_HA4 + ((0 * 2 + 1) * 8 + m) * 1024))[off];
        unsigned ur = ((const unsigned*)(g_HA4 + ((1 * 2 + 1) * 8 + m) * 1024))[off];
        unsigned sf = (kj & 1) ? (uf >> 16) : (uf & 0xffffu);
        unsigned sr = (kj & 1) ? (ur >> 16) : (ur & 0xffffu);
        const float f  = __half2float(__ushort_as_half((unsigned short)sf));
        const float rr = __half2float(__ushort_as_half((unsigned short)sr));
        a0 += f * Wout[2 * k]     + rr * Wout[2 * (H_ + k)];
        a1 += f * Wout[2 * k + 1] + rr * Wout[2 * (H_ + k) + 1];
    }
    out[2 * b]     = a0;
    out[2 * b + 1] = a1;
}

// ---------------- launch ----------------------------------------------------
extern "C" void kernel_launch(void* const* d_in, const int* in_sizes, int n_in,
                              void* d_out, int out_size) {
    const int*   tok   = (const int*)d_in[0];
    const float* emb   = (const float*)d_in[1];
    const float* W_f   = (const float*)d_in[2];
    const float* U_f   = (const float*)d_in[3];
    const float* b_f   = (const float*)d_in[4];
    const float* W_b   = (const float*)d_in[5];
    const float* U_b   = (const float*)d_in[6];
    const float* b_b   = (const float*)d_in[7];
    const float* W_out = (const float*)d_in[8];
    const float* b_out = (const float*)d_in[9];
    float* out = (float*)d_out;

    const int smem_bytes = (4096 + 256) * sizeof(uint4);   // 69632
    cudaFuncSetAttribute(lstm_kernel, cudaFuncAttributeMaxDynamicSharedMemorySize, smem_bytes);

    zero_cnt_kernel<<<4, 256>>>();
    precompute_embW<<<dim3(16, 32, 2), 256>>>(emb, W_f, b_f, W_b, b_b);
    build_Uf16<<<256, 256>>>(U_f, U_b);
    lstm_kernel<<<128, 256, smem_bytes>>>(tok);
    output_kernel<<<1, 256>>>(W_out, b_out, out);
}